// round 16
// baseline (speedup 1.0000x reference)
#include <cuda_runtime.h>
#include <cuda_fp16.h>
#include <math.h>
#include <stdint.h>

#define Bn 4
#define C1 128
#define H1 128
#define W1 128
#define C2 64
#define L 4096      // H2*W2 patches / pixels
#define M2 2048     // C1*4*4 patch elements
#define KS 4096     // K stride for paste fp16 operands
#define KX 192      // K stride for corr fp16 triple operands (3*64)
#define SCALE_F 10.0f
#define ASCALE 1024.0f

typedef unsigned long long ull;

// ---- static device scratch, pooled & aliased (allocation-free rule) ----
// poolA (256MB):
//   phase 1 (per-batch chains): corr = single 64MB at offset 0
//                               AcTh[4] fp16 = 4 x 32MB at offset 128MB
//   phase 2 (paste/scatter):    Z[4] fp32 = 4 x 32MB at offset 0 (corr dead),
//                               AcTh[4] still live at +128MB (read by paste)
// poolB (64MB): Ac = single 64MB (dead each chain before reuse)
__device__ __align__(1024) unsigned char g_poolA[268435456];
__device__ __align__(1024) unsigned char g_poolB[67108864];
__device__ __half g_Rch[Bn][(size_t)M2 * KS];      // 64 MB paste A fp16 [b][m][k]
__device__ __half g_X3a[Bn][(size_t)L * KX];       // 6.3 MB corr A triples (h,h,l)
__device__ __half g_X3b[Bn][(size_t)L * KX];       // 6.3 MB corr B triples (h,l,h)
__device__ float g_y[Bn * C1 * H1 * W1];           // 33.5 MB pasted images
__device__ float g_pix2[Bn][L];
__device__ float g_invnorm[Bn][L];
__device__ float g_mm[Bn][L];
__device__ int   g_idx1[Bn][L];
__device__ int   g_cnt[Bn][2];
__device__ float g_cmT[Bn][M2];

__device__ __forceinline__ ull ffma2(ull a, ull b, ull c) {
    asm("fma.rn.f32x2 %0, %1, %2, %0;" : "+l"(c) : "l"(a), "l"(b));
    return c;
}
__device__ __forceinline__ ull packf2(float v) {
    ull r;
    uint32_t u = __float_as_uint(v);
    asm("mov.b64 %0, {%1, %1};" : "=l"(r) : "r"(u));
    return r;
}
__device__ __forceinline__ uint32_t smem_u32(const void* p) {
    uint32_t a;
    asm("{ .reg .u64 t; cvta.to.shared.u64 t, %1; cvt.u32.u64 %0, t; }" : "=r"(a) : "l"(p));
    return a;
}

// ---------------------------------------------------------------------------
__global__ void prep_kernel(const float* __restrict__ x2, const float* __restrict__ mask) {
    int b = blockIdx.y;
    int a = blockIdx.x * 256 + threadIdx.x;
    const float* x2b = x2 + (size_t)b * C2 * L;
    const float* maskb = mask + (size_t)b * H1 * W1;
    float s = 0.f;
#pragma unroll 16
    for (int c = 0; c < C2; c++) { float v = x2b[c * L + a]; s += v * v; }
    g_pix2[b][a] = s;

    int li = a >> 6, lj = a & 63;
    bool allzero = true;
#pragma unroll
    for (int ky = 0; ky < 4; ky++)
#pragma unroll
        for (int kx = 0; kx < 4; kx++) {
            int u = 2 * li - 1 + ky, v = 2 * lj - 1 + kx;
            if ((unsigned)u < (unsigned)H1 && (unsigned)v < (unsigned)W1) {
                if (maskb[u * W1 + v] != 0.f) allzero = false;
            }
        }
    g_mm[b][a] = allzero ? 1.f : 0.f;
}

__global__ void invnorm_kernel() {
    int b = blockIdx.y;
    int l = blockIdx.x * 256 + threadIdx.x;
    int li = l >> 6, lj = l & 63;
    float s = 0.f;
#pragma unroll
    for (int dy = -1; dy <= 1; dy++)
#pragma unroll
        for (int dx = -1; dx <= 1; dx++) {
            int i = li + dy, j = lj + dx;
            if ((unsigned)i < 64u && (unsigned)j < 64u) s += g_pix2[b][i * 64 + j];
        }
    g_invnorm[b][l] = 1.0f / fmaxf(sqrtf(s), 1e-4f);
}

__global__ void compact_kernel() {
    __shared__ int cnt1[256], off1[256];
    int b = blockIdx.x;
    int t = threadIdx.x;
    int c1 = 0;
    for (int i = 0; i < 16; i++)
        if (g_mm[b][t * 16 + i] > 0.5f) c1++;
    cnt1[t] = c1;
    __syncthreads();
    if (t == 0) {
        int s1 = 0;
        for (int i = 0; i < 256; i++) { off1[i] = s1; s1 += cnt1[i]; }
        g_cnt[b][0] = s1; g_cnt[b][1] = L - s1;
    }
    __syncthreads();
    int o1 = off1[t];
    for (int i = 0; i < 16; i++) {
        int l = t * 16 + i;
        if (g_mm[b][l] > 0.5f) g_idx1[b][o1++] = l;
    }
}

// ---------------------------------------------------------------------------
__global__ void build_X3(const float* __restrict__ x2) {
    int b = blockIdx.y;
    int m = blockIdx.x * 256 + threadIdx.x;
    const float* x2b = x2 + (size_t)b * C2 * L;
    union { __half h[24]; uint4 v[3]; } ua, ub;
#pragma unroll
    for (int cc = 0; cc < 8; cc++) {
#pragma unroll
        for (int j = 0; j < 8; j++) {
            float val = x2b[(cc * 8 + j) * L + m];
            __half h = __float2half(val);
            __half lo = __float2half(val - __half2float(h));
            ua.h[j * 3] = h;  ua.h[j * 3 + 1] = h;  ua.h[j * 3 + 2] = lo;
            ub.h[j * 3] = h;  ub.h[j * 3 + 1] = lo; ub.h[j * 3 + 2] = h;
        }
        size_t off = (size_t)m * KX + cc * 24;
        uint4* pa = (uint4*)&g_X3a[b][off];
        uint4* pb = (uint4*)&g_X3b[b][off];
#pragma unroll
        for (int q = 0; q < 3; q++) { pa[q] = ua.v[q]; pb[q] = ub.v[q]; }
    }
}

// Rch[b][m][k] = fp16 of im2col(x1)[idx1[k]][m], zero-pad k in [n1, n1p)
__global__ void build_Rc(const float* __restrict__ x1) {
    int b = blockIdx.z;
    int k = blockIdx.x * 256 + threadIdx.x;
    int m = blockIdx.y;
    int n1 = g_cnt[b][0];
    int n1p = (n1 + 31) & ~31;
    if (k >= n1p) return;
    float val = 0.f;
    if (k < n1) {
        int l = g_idx1[b][k];
        int li = l >> 6, lj = l & 63;
        int c = m >> 4, ky = (m >> 2) & 3, kx = m & 3;
        int u = 2 * li - 1 + ky, v = 2 * lj - 1 + kx;
        if ((unsigned)u < 128u && (unsigned)v < 128u)
            val = x1[((size_t)b * C1 + c) * 16384 + u * 128 + v];
    }
    g_Rch[b][(size_t)m * KS + k] = __float2half(val);
}

// cmT[m] = 1e-8 * sum over ALL 4096 patches of R[l,m]
__global__ void cmT_kernel(const float* __restrict__ x1) {
    __shared__ float red[256];
    int m = blockIdx.x, b = blockIdx.y;
    int t = threadIdx.x;
    int c = m >> 4, ky = (m >> 2) & 3, kx = m & 3;
    const float* xc = x1 + ((size_t)b * C1 + c) * (H1 * W1);
    float s = 0.f;
    for (int l = t; l < L; l += 256) {
        int li = l >> 6, lj = l & 63;
        int u = 2 * li - 1 + ky, v = 2 * lj - 1 + kx;
        if ((unsigned)u < 128u && (unsigned)v < 128u) s += xc[u * W1 + v];
    }
    red[t] = s;
    __syncthreads();
    for (int st = 128; st > 0; st >>= 1) {
        if (t < st) red[t] += red[t + st];
        __syncthreads();
    }
    if (t == 0) g_cmT[b][m] = 1e-8f * red[0];
}

// scores for active rows, 4 k per block (adjacent l -> corr rows L1/L2-hot)
__global__ void scores_kernel(const float* __restrict__ corr,
                              float* __restrict__ Ac,
                              const float* __restrict__ mask_all, int b) {
    int kg = blockIdx.y;
    int n1 = g_cnt[b][0];
    int p = blockIdx.x * 256 + threadIdx.x;
    int pi = p >> 6, pj = p & 63;
    float mav = mask_all[(size_t)b * L + p];
#pragma unroll
    for (int kk = 0; kk < 4; kk++) {
        int k = kg * 4 + kk;
        if (k >= n1) break;
        int l = g_idx1[b][k];
        int li = l >> 6, lj = l & 63;
        float s = 0.f;
#pragma unroll
        for (int dy = -1; dy <= 1; dy++)
#pragma unroll
            for (int dx = -1; dx <= 1; dx++) {
                if ((unsigned)(li + dy) < 64u && (unsigned)(lj + dx) < 64u &&
                    (unsigned)(pi + dy) < 64u && (unsigned)(pj + dx) < 64u) {
                    int o = dy * 64 + dx;
                    s += corr[(size_t)(l + o) * L + (p + o)];
                }
            }
        Ac[(size_t)k * L + p] = s * g_invnorm[b][l] * mav;
    }
}

// fused column softmax + transposed fp16 emit (online max+sum, then emit pass)
__global__ void __launch_bounds__(256) softmax_emit(const float* __restrict__ Ac,
                                                    __half* __restrict__ AcTh,
                                                    const float* __restrict__ mask_all, int b) {
    __shared__ float redM[8][32];
    __shared__ float redS[8][32];
    __shared__ float se[32][33];
    int t = threadIdx.x;
    int col = t & 31, part = t >> 5;
    int p0 = blockIdx.x * 32;
    int p = p0 + col;
    int n1 = g_cnt[b][0], n0 = g_cnt[b][1];
    int n1p = (n1 + 31) & ~31;

    float mx = 0.f, sm = 0.f;
    for (int k = part; k < n1; k += 8) {
        float v = Ac[(size_t)k * L + p];
        if (v > mx) { sm *= __expf(SCALE_F * (mx - v)); mx = v; }
        sm += __expf(SCALE_F * (v - mx));
    }
    redM[part][col] = mx;
    redS[part][col] = sm;
    __syncthreads();
    if (t < 32) {
        float gm = redM[0][t], gs = redS[0][t];
        for (int q = 1; q < 8; q++) {
            float m2 = redM[q][t], s2 = redS[q][t];
            if (m2 > gm) { gs *= __expf(SCALE_F * (gm - m2)); gm = m2; }
            gs += s2 * __expf(SCALE_F * (m2 - gm));
        }
        gs += (float)n0 * __expf(-SCALE_F * gm);
        redM[0][t] = gm;
        redS[0][t] = gs;
    }
    __syncthreads();
    mx = redM[0][col];
    float sc = (1.0f / redS[0][col]) * mask_all[(size_t)b * L + p];
    __syncthreads();

    int kx = t & 31, py = t >> 5;
    for (int k0 = 0; k0 < n1p; k0 += 32) {
#pragma unroll
        for (int i = 0; i < 4; i++) {
            int k = k0 + part + 8 * i;
            float v = 0.f;
            if (k < n1) {
                float e = __expf(SCALE_F * (Ac[(size_t)k * L + p] - mx));
                float a = fmaxf(e * sc, 1e-8f);
                v = (a - 1e-8f) * ASCALE;
            }
            se[part + 8 * i][col] = v;
        }
        __syncthreads();
#pragma unroll
        for (int i = 0; i < 4; i++) {
            int pr = py + 8 * i;
            AcTh[(size_t)(p0 + pr) * KS + k0 + kx] = __float2half(se[kx][pr]);
        }
        __syncthreads();
    }
}

// ---------------------------------------------------------------------------
// generic HMMA fp16 NT GEMM. CTA = 128 threads / 4 warps (2x2 of 64x64 warp
// tiles) -> CTA tile 128x128, BK=32, 4-stage cp.async, 3 CTAs/SM.
#define GSTAGES 4
#define ABYTES (128 * 64)
#define BBYTES (128 * 64)
#define STAGE_B (ABYTES + BBYTES)  // 16384
#define SMEM_GEMM (GSTAGES * STAGE_B)

__device__ __forceinline__ void cp_async16(uint32_t dst, const void* src) {
    asm volatile("cp.async.cg.shared.global [%0], [%1], 16;" :: "r"(dst), "l"(src) : "memory");
}
__device__ __forceinline__ void ldsm4(uint32_t& r0, uint32_t& r1, uint32_t& r2, uint32_t& r3,
                                      uint32_t a) {
    asm volatile("ldmatrix.sync.aligned.m8n8.x4.shared.b16 {%0,%1,%2,%3}, [%4];"
                 : "=r"(r0), "=r"(r1), "=r"(r2), "=r"(r3) : "r"(a));
}
__device__ __forceinline__ void mma16816(float* c, const uint32_t* a, uint32_t b0, uint32_t b1) {
    asm volatile(
        "mma.sync.aligned.m16n8k16.row.col.f32.f16.f16.f32 "
        "{%0,%1,%2,%3}, {%4,%5,%6,%7}, {%8,%9}, {%0,%1,%2,%3};"
        : "+f"(c[0]), "+f"(c[1]), "+f"(c[2]), "+f"(c[3])
        : "r"(a[0]), "r"(a[1]), "r"(a[2]), "r"(a[3]), "r"(b0), "r"(b1));
}

template<int KSTRIDE, bool PASTE>
__global__ void __launch_bounds__(128, 3) hmma_gemm(
        const __half* __restrict__ Aall, const __half* __restrict__ Ball,
        float* __restrict__ Outall,
        size_t aStride, size_t bStride, size_t oStride, int nCfix, int zofs) {
    extern __shared__ __align__(16) char smem[];
    uint32_t sb = smem_u32(smem);
    int t = threadIdx.x;
    int lane = t & 31;
    int wid = t >> 5;
    int wr = wid & 1;
    int wc = wid >> 1;
    int m0 = blockIdx.x * 128;
    int p0 = blockIdx.y * 128;
    int z = blockIdx.z + zofs;
    int nC = PASTE ? (((g_cnt[z][0] + 31) & ~31) >> 5) : nCfix;

    const __half* Abase = Aall + z * aStride + (size_t)m0 * KSTRIDE;
    const __half* Bbase = Ball + z * bStride + (size_t)p0 * KSTRIDE;
    float* Out = Outall + z * oStride;   // oStride=0 -> shared single output

    auto load_chunk = [&](int kt, int s) {
        uint32_t stage = sb + s * STAGE_B;
        int k0 = kt * 32;
#pragma unroll
        for (int i = 0; i < 4; i++) {
            int e = t + i * 128;
            int row = e >> 2, c = e & 3;
            uint32_t dst = stage + row * 64 + ((c ^ (row & 3)) << 4);
            cp_async16(dst, Abase + (size_t)row * KSTRIDE + k0 + c * 8);
        }
#pragma unroll
        for (int i = 0; i < 4; i++) {
            int e = t + i * 128;
            int row = e >> 2, c = e & 3;
            uint32_t dst = stage + ABYTES + row * 64 + ((c ^ (row & 3)) << 4);
            cp_async16(dst, Bbase + (size_t)row * KSTRIDE + k0 + c * 8);
        }
        asm volatile("cp.async.commit_group;" ::: "memory");
    };

#pragma unroll
    for (int s = 0; s < GSTAGES - 1; s++) {
        if (s < nC) load_chunk(s, s);
        else asm volatile("cp.async.commit_group;" ::: "memory");
    }

    float acc[4][8][4] = {};
    int r8 = lane & 7;
    int mat = lane >> 3;
    int rowSwz = r8 & 3;
    int rA = wr * 64 + r8 + (mat & 1) * 8;
    int rB = wc * 64 + r8 + (mat & 1) * 8;
    int chi = mat >> 1;

    for (int kt = 0; kt < nC; kt++) {
        asm volatile("cp.async.wait_group %0;" :: "n"(GSTAGES - 2) : "memory");
        __syncthreads();
        uint32_t stage = sb + (kt % GSTAGES) * STAGE_B;

        if (kt + GSTAGES - 1 < nC) load_chunk(kt + GSTAGES - 1, (kt + GSTAGES - 1) % GSTAGES);
        else asm volatile("cp.async.commit_group;" ::: "memory");

#pragma unroll
        for (int ks = 0; ks < 2; ks++) {
            int kc = ks * 2 + chi;
            uint32_t a[4][4];
            uint32_t b[4][4];
#pragma unroll
            for (int mi = 0; mi < 4; mi++) {
                int row = rA + mi * 16;
                ldsm4(a[mi][0], a[mi][1], a[mi][2], a[mi][3],
                      stage + row * 64 + ((kc ^ rowSwz) << 4));
            }
#pragma unroll
            for (int nj = 0; nj < 4; nj++) {
                int row = rB + nj * 16;
                ldsm4(b[nj][0], b[nj][1], b[nj][2], b[nj][3],
                      stage + ABYTES + row * 64 + ((kc ^ rowSwz) << 4));
            }
#pragma unroll
            for (int mi = 0; mi < 4; mi++)
#pragma unroll
                for (int nj = 0; nj < 4; nj++) {
                    mma16816(acc[mi][nj * 2],     a[mi], b[nj][0], b[nj][2]);
                    mma16816(acc[mi][nj * 2 + 1], a[mi], b[nj][1], b[nj][3]);
                }
        }
    }

    const float inv = PASTE ? (1.0f / ASCALE) : 1.0f;
    int cr = lane >> 2, cc = (lane & 3) * 2;
#pragma unroll
    for (int mi = 0; mi < 4; mi++) {
        int mbase = m0 + wr * 64 + mi * 16;
        float c0a = PASTE ? g_cmT[z][mbase + cr] : 0.f;
        float c0b = PASTE ? g_cmT[z][mbase + cr + 8] : 0.f;
#pragma unroll
        for (int ni = 0; ni < 8; ni++) {
            int p = p0 + wc * 64 + ni * 8 + cc;
            float* z0 = &Out[(size_t)(mbase + cr) * L + p];
            float* z1 = &Out[(size_t)(mbase + cr + 8) * L + p];
            *(float2*)z0 = make_float2(acc[mi][ni][0] * inv + c0a, acc[mi][ni][1] * inv + c0a);
            *(float2*)z1 = make_float2(acc[mi][ni][2] * inv + c0b, acc[mi][ni][3] * inv + c0b);
        }
    }
}

// ---------------------------------------------------------------------------
// overlap-add: y[b,c,u,v] = 0.25 * sum over <=4 covering patches of Z
__global__ void scatter_kernel(const float* __restrict__ ZAll) {
    int idx = blockIdx.x * 256 + threadIdx.x;
    int b = blockIdx.y;
    int v = idx & 127, u = (idx >> 7) & 127, c = idx >> 14;
    const float* Z = ZAll + (size_t)b * M2 * L;
    float s = 0.f;
    int ky0 = (u + 1) & 1, kx0 = (v + 1) & 1;
#pragma unroll
    for (int a = 0; a < 2; a++) {
        int ky = ky0 + 2 * a;
        int i2 = u + 1 - ky;
        if (i2 < 0 || i2 > 126) continue;
        int pi = i2 >> 1;
#pragma unroll
        for (int q = 0; q < 2; q++) {
            int kx = kx0 + 2 * q;
            int j2 = v + 1 - kx;
            if (j2 < 0 || j2 > 126) continue;
            int pj = j2 >> 1;
            int m = c * 16 + ky * 4 + kx;
            s += Z[(size_t)m * L + pi * 64 + pj];
        }
    }
    g_y[b * (C1 * H1 * W1) + idx] = 0.25f * s;
}

// final 4-group dilated 3x3 convs + bias + relu. All 73KB of this group's
// weights staged in smem once; input tile double-buffered (1 barrier/channel).
#define FC_WFLOATS (C1 * 144)                 // 18432 floats = 73728 B
#define FC_TILE 1088                          // >= 32*32, 16B-friendly
#define FC_SMEM ((FC_WFLOATS + 2 * FC_TILE) * 4)

__global__ void __launch_bounds__(256) final_conv(const float* __restrict__ w,
                                                  const float* __restrict__ bias,
                                                  float* __restrict__ out) {
    extern __shared__ __align__(16) float fsm[];
    float* sw = fsm;                          // [c][tap][16]
    float* syb = fsm + FC_WFLOATS;            // 2 x FC_TILE
    int t = threadIdx.x;
    int tv = t & 15, tu = t >> 4;
    int tile = blockIdx.x;
    int u0 = (tile >> 3) * 16, v0 = (tile & 7) * 16;
    int bg = blockIdx.y;
    int b = bg >> 2, g = bg & 3;
    int r = 1 << g;
    int Wt = 16 + 2 * r;
    const float* yb = g_y + b * (C1 * H1 * W1);

    // stage all weights once: sw[c*144 + tap*16 + oc]
    for (int e = t; e < FC_WFLOATS; e += 256) {
        int c = e / 144, q = e % 144;
        int tap = q / 16, oc = q % 16;
        sw[e] = w[((g * 16 + oc) * C1 + c) * 9 + tap];
    }

    // prefill channel 0 tile
    {
        const float* yc = yb;
        for (int e = t; e < Wt * Wt; e += 256) {
            int lu = e / Wt, lv = e % Wt;
            int gu = u0 - r + lu, gv = v0 - r + lv;
            float val = 0.f;
            if ((unsigned)gu < 128u && (unsigned)gv < 128u) val = yc[gu * 128 + gv];
            syb[lu * Wt + lv] = val;
        }
    }
    __syncthreads();

    ull acc2[8] = {};
    for (int c = 0; c < C1; c++) {
        float* cur = syb + (c & 1) * FC_TILE;
        float* nxt = syb + ((c + 1) & 1) * FC_TILE;
        if (c + 1 < C1) {
            const float* yc = yb + (c + 1) * (H1 * W1);
            for (int e = t; e < Wt * Wt; e += 256) {
                int lu = e / Wt, lv = e % Wt;
                int gu = u0 - r + lu, gv = v0 - r + lv;
                float val = 0.f;
                if ((unsigned)gu < 128u && (unsigned)gv < 128u) val = yc[gu * 128 + gv];
                nxt[lu * Wt + lv] = val;
            }
        }
        const ull* wpc = (const ull*)(sw + c * 144);
#pragma unroll
        for (int kh = 0; kh < 3; kh++)
#pragma unroll
            for (int kw = 0; kw < 3; kw++) {
                int tap = kh * 3 + kw;
                ull vv = packf2(cur[(tu + kh * r) * Wt + (tv + kw * r)]);
                const ull* wp = wpc + tap * 8;
#pragma unroll
                for (int pr = 0; pr < 8; pr++)
                    acc2[pr] = ffma2(vv, wp[pr], acc2[pr]);
            }
        __syncthreads();
    }
    int u = u0 + tu, v = v0 + tv;
#pragma unroll
    for (int pr = 0; pr < 8; pr++) {
        union { ull u64; float2 f; } cv; cv.u64 = acc2[pr];
        int oc0 = pr * 2;
        float o0 = fmaxf(cv.f.x + bias[g * 16 + oc0], 0.f);
        float o1 = fmaxf(cv.f.y + bias[g * 16 + oc0 + 1], 0.f);
        out[((b * 64 + g * 16 + oc0) * 128 + u) * 128 + v] = o0;
        out[((b * 64 + g * 16 + oc0 + 1) * 128 + u) * 128 + v] = o1;
    }
}

// ---------------------------------------------------------------------------
extern "C" void kernel_launch(void* const* d_in, const int* in_sizes, int n_in,
                              void* d_out, int out_size) {
    (void)in_sizes; (void)n_in; (void)out_size;
    const float* x1       = (const float*)d_in[0];
    const float* x2       = (const float*)d_in[1];
    const float* mask     = (const float*)d_in[2];
    const float* mask_all = (const float*)d_in[3];
    const float* conv_w   = (const float*)d_in[4];
    const float* conv_b   = (const float*)d_in[5];
    float* out = (float*)d_out;

    cudaFuncSetAttribute(hmma_gemm<KS, true>,  cudaFuncAttributeMaxDynamicSharedMemorySize, SMEM_GEMM);
    cudaFuncSetAttribute(hmma_gemm<KX, false>, cudaFuncAttributeMaxDynamicSharedMemorySize, SMEM_GEMM);
    cudaFuncSetAttribute(final_conv, cudaFuncAttributeMaxDynamicSharedMemorySize, FC_SMEM);

    unsigned char* pA; cudaGetSymbolAddress((void**)&pA, g_poolA);
    unsigned char* pB; cudaGetSymbolAddress((void**)&pB, g_poolB);
    __half* d_X3a;  cudaGetSymbolAddress((void**)&d_X3a, g_X3a);
    __half* d_X3b;  cudaGetSymbolAddress((void**)&d_X3b, g_X3b);
    __half* d_Rch;  cudaGetSymbolAddress((void**)&d_Rch, g_Rch);

    float*  d_corr = (float*)pA;                       // single 64MB, phase 1 (inside Z region)
    float*  d_Z    = (float*)pA;                       // phase 2, first 128MB
    __half* d_AcTh = (__half*)(pA + 134217728);        // +128MB, 4 x 32MB (disjoint from corr)
    float*  d_Ac   = (float*)pB;                       // single 64MB

    // single fork-join stream (proven topology, rounds 10-13)
    cudaStream_t s2;
    cudaStreamCreateWithFlags(&s2, cudaStreamNonBlocking);
    cudaEvent_t evA, evB;
    cudaEventCreateWithFlags(&evA, cudaEventDisableTiming);
    cudaEventCreateWithFlags(&evB, cudaEventDisableTiming);

    prep_kernel<<<dim3(16, Bn), 256>>>(x2, mask);
    build_X3<<<dim3(16, Bn), 256>>>(x2);
    compact_kernel<<<Bn, 256>>>();
    invnorm_kernel<<<dim3(16, Bn), 256>>>();

    // fork: build_Rc + cmT overlap the corr/scores/softmax chains on s2
    cudaEventRecord(evA, 0);
    cudaStreamWaitEvent(s2, evA, 0);
    build_Rc<<<dim3(16, M2, Bn), 256, 0, s2>>>(x1);
    cmT_kernel<<<dim3(M2, Bn), 256, 0, s2>>>(x1);
    cudaEventRecord(evB, s2);

    // per-batch chains on the default stream. corr + Ac are single shared
    // buffers (dead before the next chain); AcTh_b regions are disjoint from
    // corr (offset >= 128MB), so the phase aliasing is race-free.
    for (int b = 0; b < Bn; b++) {
        __half* AcTh_b = d_AcTh + (size_t)b * L * KS;
        hmma_gemm<KX, false><<<dim3(32, 32, 1), 128, SMEM_GEMM>>>(
            d_X3a, d_X3b, d_corr, (size_t)L * KX, (size_t)L * KX, /*oStride=*/0, KX / 32, b);
        scores_kernel<<<dim3(16, 1024), 256>>>(d_corr, d_Ac, mask_all, b);
        softmax_emit<<<128, 256>>>(d_Ac, AcTh_b, mask_all, b);
    }
    cudaStreamWaitEvent(0, evB, 0);

    // paste: M=2048, N=4096, K=n1 (padded), batched z=4; Z overwrites corr (dead)
    hmma_gemm<KS, true><<<dim3(16, 32, Bn), 128, SMEM_GEMM>>>(
        d_Rch, d_AcTh, d_Z, (size_t)M2 * KS, (size_t)L * KS, (size_t)M2 * L, 0, 0);
    scatter_kernel<<<dim3(8192, Bn), 256>>>(d_Z);
    final_conv<<<dim3(64, 16), 256, FC_SMEM>>>(conv_w, conv_b, out);
}